// round 1
// baseline (speedup 1.0000x reference)
#include <cuda_runtime.h>
#include <math.h>
#include <float.h>

// ---------------- problem constants ----------------
#define Bb 2
#define Tt 2048
#define DM 2048
#define Hh 16
#define HD 128
#define KVL 512
#define QL 1024
#define Rr 64
#define MROWS (Bb*Tt)        // 4096

// ---------------- scratch (device globals; no cudaMalloc allowed) ----------
__device__ float g_Kc[MROWS * (Hh*HD)];   // (b t, h hd)  33.5 MB
__device__ float g_V [MROWS * (Hh*HD)];   // 33.5 MB
__device__ float g_cQ[MROWS * QL];        // 16.8 MB
__device__ float g_Qc[MROWS * (Hh*HD)];   // 33.5 MB
__device__ float g_Qr[MROWS * (Hh*Rr)];   // 16.8 MB
__device__ float g_KR[MROWS * Rr];        // 1 MB (pre-rope)
__device__ float g_AO[MROWS * (Hh*HD)];   // 33.5 MB

// ---------------- SGEMM: C[M,N] = A[M,K] @ B[K,N], row-major ---------------
// 128x128 block tile, BK=16, 256 threads, 8x8 microtile per thread.
__global__ __launch_bounds__(256) void sgemm_kernel(
    const float* __restrict__ A, const float* __restrict__ B,
    float* __restrict__ C, int M, int N, int K)
{
    constexpr int BM = 128, BN = 128, BK = 16;
    __shared__ __align__(16) float As[BK * (BM + 4)];
    __shared__ __align__(16) float Bs[BK * BN];

    const int tid = threadIdx.x;
    const int bm  = blockIdx.y * BM;
    const int bn  = blockIdx.x * BN;
    const int tx  = tid & 15;      // 16 col groups
    const int ty  = tid >> 4;      // 16 row groups

    // load mapping
    const int arow0 = tid >> 2;           // 0..63
    const int acol  = (tid & 3) * 4;      // 0,4,8,12
    const int brow0 = tid >> 5;           // 0..7
    const int bcol  = (tid & 31) * 4;     // 0..124

    float acc[8][8];
    #pragma unroll
    for (int i = 0; i < 8; i++)
        #pragma unroll
        for (int j = 0; j < 8; j++) acc[i][j] = 0.0f;

    for (int k0 = 0; k0 < K; k0 += BK) {
        // A tile -> transposed smem As[kk][row]
        #pragma unroll
        for (int i = 0; i < 2; i++) {
            int r = arow0 + i * 64;
            float4 v = *reinterpret_cast<const float4*>(
                &A[(size_t)(bm + r) * K + k0 + acol]);
            As[(acol + 0) * (BM + 4) + r] = v.x;
            As[(acol + 1) * (BM + 4) + r] = v.y;
            As[(acol + 2) * (BM + 4) + r] = v.z;
            As[(acol + 3) * (BM + 4) + r] = v.w;
        }
        // B tile -> Bs[kk][col]
        #pragma unroll
        for (int i = 0; i < 2; i++) {
            int r = brow0 + i * 8;
            float4 v = make_float4(0.f, 0.f, 0.f, 0.f);
            if (bn + bcol < N)
                v = *reinterpret_cast<const float4*>(
                    &B[(size_t)(k0 + r) * N + bn + bcol]);
            *reinterpret_cast<float4*>(&Bs[r * BN + bcol]) = v;
        }
        __syncthreads();

        #pragma unroll
        for (int kk = 0; kk < BK; kk++) {
            float4 a0 = *reinterpret_cast<const float4*>(&As[kk * (BM + 4) + ty * 8]);
            float4 a1 = *reinterpret_cast<const float4*>(&As[kk * (BM + 4) + ty * 8 + 4]);
            float4 b0 = *reinterpret_cast<const float4*>(&Bs[kk * BN + tx * 4]);
            float4 b1 = *reinterpret_cast<const float4*>(&Bs[kk * BN + 64 + tx * 4]);
            float av[8] = {a0.x, a0.y, a0.z, a0.w, a1.x, a1.y, a1.z, a1.w};
            float bv[8] = {b0.x, b0.y, b0.z, b0.w, b1.x, b1.y, b1.z, b1.w};
            #pragma unroll
            for (int i = 0; i < 8; i++)
                #pragma unroll
                for (int j = 0; j < 8; j++)
                    acc[i][j] = fmaf(av[i], bv[j], acc[i][j]);
        }
        __syncthreads();
    }

    // store: thread cols = bn + tx*4 + {0..3}  and  bn + 64 + tx*4 + {0..3}
    #pragma unroll
    for (int i = 0; i < 8; i++) {
        int row = bm + ty * 8 + i;
        int c0 = bn + tx * 4;
        int c1 = bn + 64 + tx * 4;
        if (c0 < N) {
            float4 v = make_float4(acc[i][0], acc[i][1], acc[i][2], acc[i][3]);
            *reinterpret_cast<float4*>(&C[(size_t)row * N + c0]) = v;
        }
        if (c1 < N) {
            float4 v = make_float4(acc[i][4], acc[i][5], acc[i][6], acc[i][7]);
            *reinterpret_cast<float4*>(&C[(size_t)row * N + c1]) = v;
        }
    }
}

// ---------------- rope kernels ----------------
// Q_r layout: (b t, h*64 + r). pairs: idx over MROWS * H * 32
__global__ __launch_bounds__(256) void rope_q_kernel(
    float* __restrict__ Qr, const float* __restrict__ freqs)
{
    int idx = blockIdx.x * 256 + threadIdx.x;
    if (idx >= MROWS * Hh * (Rr / 2)) return;
    int m   = idx >> 9;            // / (16*32)
    int rem = idx & 511;
    int h   = rem >> 5;
    int i   = rem & 31;
    int t   = m & (Tt - 1);
    float f = freqs[t * (Rr / 2) + i];
    float s, c;
    sincosf(f, &s, &c);
    size_t base = (size_t)m * (Hh * Rr) + h * Rr + 2 * i;
    float x0 = Qr[base], x1 = Qr[base + 1];
    Qr[base]     = x0 * c - x1 * s;
    Qr[base + 1] = x0 * s + x1 * c;
}

// K_r: in (b t, 64) pre-rope -> out (b t, 64) roped (this is an output too)
__global__ __launch_bounds__(256) void rope_k_kernel(
    const float* __restrict__ KRin, const float* __restrict__ freqs,
    float* __restrict__ KRout)
{
    int idx = blockIdx.x * 256 + threadIdx.x;
    if (idx >= MROWS * (Rr / 2)) return;
    int m = idx >> 5;
    int i = idx & 31;
    int t = m & (Tt - 1);
    float f = freqs[t * (Rr / 2) + i];
    float s, c;
    sincosf(f, &s, &c);
    size_t base = (size_t)m * Rr + 2 * i;
    float x0 = KRin[base], x1 = KRin[base + 1];
    KRout[base]     = x0 * c - x1 * s;
    KRout[base + 1] = x0 * s + x1 * c;
}

// ---------------- flash attention (fp32, causal) ----------------
// grid: (T/64, H, B), block: 256.  Q tile 64 x 192, K tile 64 x 192, V 64 x 128.
// Thread (ty,tx): S rows ty*4+ri, S cols tx + cj*16. O cols: {tx*4..+3, 64+tx*4..+3}.
#define SQS 196
#define SKS 196
#define SVS 132
#define SPS 68
#define FLASH_SMEM ((64*(SQS+SKS+SVS+SPS))*4)

__global__ __launch_bounds__(256) void flash_kernel(
    const float* __restrict__ Qc, const float* __restrict__ Qr,
    const float* __restrict__ Kc, const float* __restrict__ Kr,
    const float* __restrict__ V,  float* __restrict__ O)
{
    extern __shared__ float sm[];
    float* sQ = sm;
    float* sK = sQ + 64 * SQS;
    float* sV = sK + 64 * SKS;
    float* sP = sV + 64 * SVS;

    const int qt = blockIdx.x, h = blockIdx.y, b = blockIdx.z;
    const int q0 = qt * 64;
    const int tid = threadIdx.x;
    const int tx = tid & 15, ty = tid >> 4;
    const float scale = 0.07216878364870323f;  // 1/sqrt(192)

    // load Q tile: 64 rows x 192 cols (128 from Qc, 64 from Qr)
    for (int idx = tid; idx < 64 * 48; idx += 256) {
        int r = idx / 48, c4 = (idx % 48) * 4;
        int m = b * Tt + q0 + r;
        float4 v;
        if (c4 < 128)
            v = *reinterpret_cast<const float4*>(&Qc[(size_t)m * (Hh*HD) + h * HD + c4]);
        else
            v = *reinterpret_cast<const float4*>(&Qr[(size_t)m * (Hh*Rr) + h * Rr + (c4 - 128)]);
        *reinterpret_cast<float4*>(&sQ[r * SQS + c4]) = v;
    }

    float o[2][4][4];
    #pragma unroll
    for (int hf = 0; hf < 2; hf++)
        #pragma unroll
        for (int ri = 0; ri < 4; ri++)
            #pragma unroll
            for (int j = 0; j < 4; j++) o[hf][ri][j] = 0.0f;
    float mrow[4] = {-INFINITY, -INFINITY, -INFINITY, -INFINITY};
    float lrow[4] = {0.f, 0.f, 0.f, 0.f};

    for (int kt = 0; kt <= qt; kt++) {
        const int k0 = kt * 64;
        __syncthreads();  // protect sK/sV/sP reuse
        // load K tile
        for (int idx = tid; idx < 64 * 48; idx += 256) {
            int r = idx / 48, c4 = (idx % 48) * 4;
            int mk = b * Tt + k0 + r;
            float4 v;
            if (c4 < 128)
                v = *reinterpret_cast<const float4*>(&Kc[(size_t)mk * (Hh*HD) + h * HD + c4]);
            else
                v = *reinterpret_cast<const float4*>(&Kr[(size_t)mk * Rr + (c4 - 128)]);
            *reinterpret_cast<float4*>(&sK[r * SKS + c4]) = v;
        }
        // load V tile
        for (int idx = tid; idx < 64 * 32; idx += 256) {
            int r = idx / 32, c4 = (idx % 32) * 4;
            int mk = b * Tt + k0 + r;
            *reinterpret_cast<float4*>(&sV[r * SVS + c4]) =
                *reinterpret_cast<const float4*>(&V[(size_t)mk * (Hh*HD) + h * HD + c4]);
        }
        __syncthreads();

        // ---- S = Q K^T (64x64 per tile, microtile 4x4 per thread) ----
        float s[4][4];
        #pragma unroll
        for (int ri = 0; ri < 4; ri++)
            #pragma unroll
            for (int cj = 0; cj < 4; cj++) s[ri][cj] = 0.0f;

        #pragma unroll 4
        for (int k4 = 0; k4 < 192; k4 += 4) {
            float4 a[4], bb[4];
            #pragma unroll
            for (int ri = 0; ri < 4; ri++)
                a[ri] = *reinterpret_cast<const float4*>(&sQ[(ty * 4 + ri) * SQS + k4]);
            #pragma unroll
            for (int cj = 0; cj < 4; cj++)
                bb[cj] = *reinterpret_cast<const float4*>(&sK[(tx + cj * 16) * SKS + k4]);
            #pragma unroll
            for (int ri = 0; ri < 4; ri++)
                #pragma unroll
                for (int cj = 0; cj < 4; cj++) {
                    s[ri][cj] = fmaf(a[ri].x, bb[cj].x, s[ri][cj]);
                    s[ri][cj] = fmaf(a[ri].y, bb[cj].y, s[ri][cj]);
                    s[ri][cj] = fmaf(a[ri].z, bb[cj].z, s[ri][cj]);
                    s[ri][cj] = fmaf(a[ri].w, bb[cj].w, s[ri][cj]);
                }
        }

        // scale + causal mask (only diagonal tile can mask)
        const bool diag = (kt == qt);
        #pragma unroll
        for (int ri = 0; ri < 4; ri++) {
            int qg = q0 + ty * 4 + ri;
            #pragma unroll
            for (int cj = 0; cj < 4; cj++) {
                int kg = k0 + tx + cj * 16;
                s[ri][cj] *= scale;
                if (diag && kg > qg) s[ri][cj] = -INFINITY;
            }
        }

        // online softmax per row (reduce across the 16 tx lanes)
        #pragma unroll
        for (int ri = 0; ri < 4; ri++) {
            float mx = fmaxf(fmaxf(s[ri][0], s[ri][1]), fmaxf(s[ri][2], s[ri][3]));
            #pragma unroll
            for (int off = 8; off >= 1; off >>= 1)
                mx = fmaxf(mx, __shfl_xor_sync(0xffffffffu, mx, off));
            float mnew = fmaxf(mrow[ri], mx);
            float p0 = __expf(s[ri][0] - mnew);
            float p1 = __expf(s[ri][1] - mnew);
            float p2 = __expf(s[ri][2] - mnew);
            float p3 = __expf(s[ri][3] - mnew);
            float rs = p0 + p1 + p2 + p3;
            #pragma unroll
            for (int off = 8; off >= 1; off >>= 1)
                rs += __shfl_xor_sync(0xffffffffu, rs, off);
            float alpha = __expf(mrow[ri] - mnew);
            lrow[ri] = lrow[ri] * alpha + rs;
            mrow[ri] = mnew;
            #pragma unroll
            for (int hf = 0; hf < 2; hf++)
                #pragma unroll
                for (int j = 0; j < 4; j++) o[hf][ri][j] *= alpha;
            int prow = (ty * 4 + ri) * SPS + tx;
            sP[prow +  0] = p0;
            sP[prow + 16] = p1;
            sP[prow + 32] = p2;
            sP[prow + 48] = p3;
        }
        __syncthreads();

        // ---- O += P @ V ----
        #pragma unroll 2
        for (int j4 = 0; j4 < 64; j4 += 4) {
            float pvv[4][4];
            #pragma unroll
            for (int ri = 0; ri < 4; ri++) {
                float4 t4 = *reinterpret_cast<const float4*>(&sP[(ty * 4 + ri) * SPS + j4]);
                pvv[ri][0] = t4.x; pvv[ri][1] = t4.y; pvv[ri][2] = t4.z; pvv[ri][3] = t4.w;
            }
            #pragma unroll
            for (int jj = 0; jj < 4; jj++) {
                float4 v0 = *reinterpret_cast<const float4*>(&sV[(j4 + jj) * SVS + tx * 4]);
                float4 v1 = *reinterpret_cast<const float4*>(&sV[(j4 + jj) * SVS + 64 + tx * 4]);
                #pragma unroll
                for (int ri = 0; ri < 4; ri++) {
                    float p = pvv[ri][jj];
                    o[0][ri][0] = fmaf(p, v0.x, o[0][ri][0]);
                    o[0][ri][1] = fmaf(p, v0.y, o[0][ri][1]);
                    o[0][ri][2] = fmaf(p, v0.z, o[0][ri][2]);
                    o[0][ri][3] = fmaf(p, v0.w, o[0][ri][3]);
                    o[1][ri][0] = fmaf(p, v1.x, o[1][ri][0]);
                    o[1][ri][1] = fmaf(p, v1.y, o[1][ri][1]);
                    o[1][ri][2] = fmaf(p, v1.z, o[1][ri][2]);
                    o[1][ri][3] = fmaf(p, v1.w, o[1][ri][3]);
                }
            }
        }
    }

    // epilogue: normalize and write (b t, h hd)
    #pragma unroll
    for (int ri = 0; ri < 4; ri++) {
        float inv = 1.0f / lrow[ri];
        int m = b * Tt + q0 + ty * 4 + ri;
        float4 r0 = make_float4(o[0][ri][0] * inv, o[0][ri][1] * inv,
                                o[0][ri][2] * inv, o[0][ri][3] * inv);
        float4 r1 = make_float4(o[1][ri][0] * inv, o[1][ri][1] * inv,
                                o[1][ri][2] * inv, o[1][ri][3] * inv);
        *reinterpret_cast<float4*>(&O[(size_t)m * (Hh*HD) + h * HD + tx * 4]) = r0;
        *reinterpret_cast<float4*>(&O[(size_t)m * (Hh*HD) + h * HD + 64 + tx * 4]) = r1;
    }
}

// ---------------- launch ----------------
static inline dim3 gemm_grid(int M, int N) {
    return dim3((N + 127) / 128, (M + 127) / 128);
}

extern "C" void kernel_launch(void* const* d_in, const int* in_sizes, int n_in,
                              void* d_out, int out_size)
{
    const float* x     = (const float*)d_in[0];
    const float* freqs = (const float*)d_in[1];
    const float* W_DKV = (const float*)d_in[2];
    const float* W_UK  = (const float*)d_in[3];
    const float* W_UV  = (const float*)d_in[4];
    const float* W_KR  = (const float*)d_in[5];
    const float* W_DQ  = (const float*)d_in[6];
    const float* W_UQ  = (const float*)d_in[7];
    const float* W_QR  = (const float*)d_in[8];
    const float* W_O   = (const float*)d_in[9];

    float* y    = (float*)d_out;                         // (B,T,DM)
    float* cKV  = y   + (size_t)Bb * Tt * DM;            // (B,T,KVL)
    float* KRo  = cKV + (size_t)Bb * Tt * KVL;           // (B,T,R)

    float *pKc, *pV, *pcQ, *pQc, *pQr, *pKR, *pAO;
    cudaGetSymbolAddress((void**)&pKc, g_Kc);
    cudaGetSymbolAddress((void**)&pV,  g_V);
    cudaGetSymbolAddress((void**)&pcQ, g_cQ);
    cudaGetSymbolAddress((void**)&pQc, g_Qc);
    cudaGetSymbolAddress((void**)&pQr, g_Qr);
    cudaGetSymbolAddress((void**)&pKR, g_KR);
    cudaGetSymbolAddress((void**)&pAO, g_AO);

    // opt-in to large dynamic smem for flash kernel (persistent; also called
    // before capture on the correctness run)
    cudaFuncSetAttribute(flash_kernel,
                         cudaFuncAttributeMaxDynamicSharedMemorySize, FLASH_SMEM);

    // 1. c_KV = x @ W_DKV  -> output region
    sgemm_kernel<<<gemm_grid(MROWS, KVL), 256>>>(x, W_DKV, cKV, MROWS, KVL, DM);
    // 2. K_c = c_KV @ W_UK
    sgemm_kernel<<<gemm_grid(MROWS, Hh*HD), 256>>>(cKV, W_UK, pKc, MROWS, Hh*HD, KVL);
    // 3. V = c_KV @ W_UV
    sgemm_kernel<<<gemm_grid(MROWS, Hh*HD), 256>>>(cKV, W_UV, pV, MROWS, Hh*HD, KVL);
    // 4. x @ W_KR
    sgemm_kernel<<<gemm_grid(MROWS, Rr), 256>>>(x, W_KR, pKR, MROWS, Rr, DM);
    // 5. rope -> K_r output region
    {
        int n = MROWS * (Rr / 2);
        rope_k_kernel<<<(n + 255) / 256, 256>>>(pKR, freqs, KRo);
    }
    // 6. c_Q = x @ W_DQ
    sgemm_kernel<<<gemm_grid(MROWS, QL), 256>>>(x, W_DQ, pcQ, MROWS, QL, DM);
    // 7. Q_c = c_Q @ W_UQ
    sgemm_kernel<<<gemm_grid(MROWS, Hh*HD), 256>>>(pcQ, W_UQ, pQc, MROWS, Hh*HD, QL);
    // 8. Q_r raw = c_Q @ W_QR
    sgemm_kernel<<<gemm_grid(MROWS, Hh*Rr), 256>>>(pcQ, W_QR, pQr, MROWS, Hh*Rr, QL);
    // 9. rope Q_r in place
    {
        int n = MROWS * Hh * (Rr / 2);
        rope_q_kernel<<<(n + 255) / 256, 256>>>(pQr, freqs);
    }
    // 10. flash attention -> g_AO  (b t, h hd)
    {
        dim3 grid(Tt / 64, Hh, Bb);
        flash_kernel<<<grid, 256, FLASH_SMEM>>>(pQc, pQr, pKc, KRo, pV, pAO);
    }
    // 11. y = AO @ W_O
    sgemm_kernel<<<gemm_grid(MROWS, DM), 256>>>(pAO, W_O, y, MROWS, DM, Hh*HD);
}

// round 3
// speedup vs baseline: 1.1854x; 1.1854x over previous
#include <cuda_runtime.h>
#include <math.h>
#include <float.h>
#include <stdint.h>

// ---------------- problem constants ----------------
#define Bb 2
#define Tt 2048
#define DM 2048
#define Hh 16
#define HD 128
#define KVL 512
#define QL 1024
#define Rr 64
#define MROWS (Bb*Tt)        // 4096

#if defined(__CUDA_ARCH_FEAT_SM103_ALL) || defined(__CUDA_ARCH_FEAT_SM100_ALL)
#define HAS_TCGEN05 1
#else
#define HAS_TCGEN05 0
#endif

// ---------------- scratch (device globals) ----------
__device__ float g_Kc[MROWS * (Hh*HD)];
__device__ float g_V [MROWS * (Hh*HD)];
__device__ float g_cQ[MROWS * QL];
__device__ float g_Qc[MROWS * (Hh*HD)];
__device__ float g_Qr[MROWS * (Hh*Rr)];
__device__ float g_KR[MROWS * Rr];
__device__ float g_AO[MROWS * (Hh*HD)];
// transposed weights (concatenated)
#define O_DKV 0
#define O_UK  (O_DKV + 512*2048)
#define O_UV  (O_UK  + 2048*512)
#define O_KR  (O_UV  + 2048*512)
#define O_DQ  (O_KR  + 64*2048)
#define O_UQ  (O_DQ  + 1024*2048)
#define O_QR  (O_UQ  + 2048*1024)
#define O_O   (O_QR  + 2048*1024)
#define WT_TOTAL (O_O + 2048*2048)
__device__ float g_Wt[WT_TOTAL];

// ---------------- PTX helpers (tcgen05 gated) ----------------
__device__ __forceinline__ uint32_t smem_u32(const void* p) {
    uint32_t a;
    asm("{ .reg .u64 t; cvta.to.shared.u64 t, %1; cvt.u32.u64 %0, t; }"
        : "=r"(a) : "l"(p));
    return a;
}

#if HAS_TCGEN05
__device__ __forceinline__ bool elect1() {
    uint32_t r;
    asm volatile("{\n\t.reg .pred p;\n\telect.sync _|p, 0xFFFFFFFF;\n\t"
                 "selp.b32 %0,1,0,p;\n\t}" : "=r"(r));
    return r != 0;
}
#define MBAR_INIT(a, c) \
    asm volatile("mbarrier.init.shared.b64 [%0], %1;" :: "r"(a), "r"(c) : "memory")
#define MBAR_WAIT(a, ph) do { \
    uint32_t _m = (a), _p = (uint32_t)(ph), _d; \
    asm volatile("{\n\t.reg .pred p;\n\t" \
        "mbarrier.try_wait.parity.acquire.cta.shared::cta.b64 p, [%1], %2;\n\t" \
        "selp.b32 %0,1,0,p;\n\t}" : "=r"(_d) : "r"(_m), "r"(_p) : "memory"); \
    while (!_d) { \
        asm volatile("{\n\t.reg .pred p;\n\t" \
            "mbarrier.try_wait.parity.acquire.cta.shared::cta.b64 p, [%1], %2, 0x989680;\n\t" \
            "selp.b32 %0,1,0,p;\n\t}" : "=r"(_d) : "r"(_m), "r"(_p) : "memory"); \
    } } while (0)
#define T5_COMMIT(a) \
    asm volatile("tcgen05.commit.cta_group::1.mbarrier::arrive::one.shared::cluster.b64 [%0];" \
                 :: "r"(a) : "memory")
#define T5_ALLOC(a, n) \
    asm volatile("tcgen05.alloc.cta_group::1.sync.aligned.shared::cta.b32 [%0], %1;" \
                 :: "r"(a), "r"(n) : "memory")
#define T5_DEALLOC(t, n) \
    asm volatile("tcgen05.dealloc.cta_group::1.sync.aligned.b32 %0, %1;" :: "r"(t), "r"(n))
#define T5_RELINQ() \
    asm volatile("tcgen05.relinquish_alloc_permit.cta_group::1.sync.aligned;")
#define T5_WAIT_LD()   asm volatile("tcgen05.wait::ld.sync.aligned;" ::: "memory")
#define T5_FENCE_AFTER() asm volatile("tcgen05.fence::after_thread_sync;" ::: "memory")
#define FENCE_ASYNC()  asm volatile("fence.proxy.async.shared::cta;" ::: "memory")

#define LDTM_X32(r, addr) \
    asm volatile("tcgen05.ld.sync.aligned.32x32b.x32.b32 " \
        "{%0, %1, %2, %3, %4, %5, %6, %7, %8, %9, %10, %11, %12, %13, %14, %15, " \
        "%16, %17, %18, %19, %20, %21, %22, %23, %24, %25, %26, %27, %28, %29, %30, %31}, [%32];" \
        : "=r"((r)[0]),  "=r"((r)[1]),  "=r"((r)[2]),  "=r"((r)[3]), \
          "=r"((r)[4]),  "=r"((r)[5]),  "=r"((r)[6]),  "=r"((r)[7]), \
          "=r"((r)[8]),  "=r"((r)[9]),  "=r"((r)[10]), "=r"((r)[11]), \
          "=r"((r)[12]), "=r"((r)[13]), "=r"((r)[14]), "=r"((r)[15]), \
          "=r"((r)[16]), "=r"((r)[17]), "=r"((r)[18]), "=r"((r)[19]), \
          "=r"((r)[20]), "=r"((r)[21]), "=r"((r)[22]), "=r"((r)[23]), \
          "=r"((r)[24]), "=r"((r)[25]), "=r"((r)[26]), "=r"((r)[27]), \
          "=r"((r)[28]), "=r"((r)[29]), "=r"((r)[30]), "=r"((r)[31]) \
        : "r"(addr))

__device__ __forceinline__ void mma_tf32(uint32_t d, uint64_t ad, uint64_t bd,
                                         uint32_t idesc, uint32_t en) {
    asm volatile("{\n\t.reg .pred p;\n\tsetp.ne.u32 p, %4, 0;\n\t"
        "tcgen05.mma.cta_group::1.kind::tf32 [%0], %1, %2, %3, p;\n\t}"
        :: "r"(d), "l"(ad), "l"(bd), "r"(idesc), "r"(en) : "memory");
}
__device__ __forceinline__ uint64_t mk_desc(uint32_t addr) {
    // SW128 K-major: layout=2, version=1, SBO=64, LBO=1
    return ((uint64_t)2 << 61) | ((uint64_t)1 << 46) | ((uint64_t)64 << 32)
         | ((uint64_t)1 << 16) | ((addr >> 4) & 0x3FFF);
}
#endif  // HAS_TCGEN05

__device__ __forceinline__ void split2(float v, uint32_t& h, uint32_t& l) {
    uint32_t u = __float_as_uint(v);
    h = u & 0xFFFFE000u;                         // exact tf32 truncation
    l = __float_as_uint(v - __uint_as_float(h)); // exact residual
}
__device__ __forceinline__ void sts128(uint32_t addr, uint32_t a, uint32_t b,
                                       uint32_t c, uint32_t d) {
    asm volatile("st.shared.v4.b32 [%0], {%1,%2,%3,%4};"
                 :: "r"(addr), "r"(a), "r"(b), "r"(c), "r"(d) : "memory");
}

// ---------------- weight transpose: Wt[n][k] = W[k][n] ----------------
__global__ __launch_bounds__(256) void transpose_kernel(
    const float* __restrict__ W, float* __restrict__ Wt, int K, int N)
{
    __shared__ float t[32][33];
    int n0 = blockIdx.x * 32, k0 = blockIdx.y * 32;
    #pragma unroll
    for (int i = threadIdx.y; i < 32; i += 8)
        t[i][threadIdx.x] = W[(size_t)(k0 + i) * N + n0 + threadIdx.x];
    __syncthreads();
    #pragma unroll
    for (int i = threadIdx.y; i < 32; i += 8)
        Wt[(size_t)(n0 + i) * K + k0 + threadIdx.x] = t[threadIdx.x][i];
}

// ---------------- GEMM: C[M,N] = A[M,K] @ Bt[N,K]^T ----------------
// tcgen05 tf32x3 path on sm_103a; SIMT fallback on plain targets (never
// expected to execute at runtime — exact-match cubin wins).
template<int TN>
__global__ __launch_bounds__(128) void tgemm_kernel(
    const float* __restrict__ A, const float* __restrict__ Bt,
    float* __restrict__ C, int N, int K)
{
#if HAS_TCGEN05
    constexpr int A_BYTES = 128 * 128;     // 128 rows x 32 tf32 (SW128)
    constexpr int B_BYTES = TN * 128;
    constexpr int STAGE = 2 * A_BYTES + 2 * B_BYTES;
    extern __shared__ char smem[];
    const uint32_t sbase = smem_u32(smem);
    const uint32_t mb_empty = sbase;            // 3 mbarriers, 8B each
    const uint32_t mb_done  = sbase + 24;
    const uint32_t tmem_slot = sbase + 32;
    const uint32_t tiles = (sbase + 64 + 1023) & ~1023u;  // 1024-aligned

    const int tid = threadIdx.x;
    const int bm = blockIdx.y * 128, bn = blockIdx.x * TN;

    if (tid == 0) {
        MBAR_INIT(mb_empty + 0, 1);
        MBAR_INIT(mb_empty + 8, 1);
        MBAR_INIT(mb_empty + 16, 1);
        MBAR_INIT(mb_done, 1);
    }
    if (tid < 32) {
        T5_ALLOC(tmem_slot, 128);
        T5_RELINQ();
    }
    __syncthreads();
    uint32_t tmem;
    asm volatile("ld.shared.b32 %0, [%1];" : "=r"(tmem) : "r"(tmem_slot));

    const uint32_t idesc = (1u << 4) | (2u << 7) | (2u << 10)
                         | ((uint32_t)(TN / 8) << 17) | (8u << 24);
    const int nc = K >> 5;

    for (int c = 0; c < nc; c++) {
        const int s = c - (c / 3) * 3;
        const uint32_t st = tiles + s * STAGE;
        if (c >= 3) {
            MBAR_WAIT(mb_empty + 8 * s, ((c / 3) - 1) & 1);
        }
        const int k0 = c * 32;
        // A tile: 128 rows x 32 floats, 8 float4/thread (hi+lo)
        #pragma unroll
        for (int i = 0; i < 8; i++) {
            int idx = i * 128 + tid;
            int row = idx >> 3, seg = idx & 7;
            float4 v = *reinterpret_cast<const float4*>(
                &A[(size_t)(bm + row) * K + k0 + seg * 4]);
            uint32_t hx, lx, hy, ly, hz, lz, hw, lw;
            split2(v.x, hx, lx); split2(v.y, hy, ly);
            split2(v.z, hz, lz); split2(v.w, hw, lw);
            uint32_t byte = row * 128 + seg * 16;
            uint32_t sw = byte ^ ((byte >> 3) & 0x70);
            sts128(st + sw, hx, hy, hz, hw);
            sts128(st + A_BYTES + sw, lx, ly, lz, lw);
        }
        // B tile: TN rows x 32 floats
        #pragma unroll
        for (int i = 0; i < TN / 16; i++) {
            int idx = i * 128 + tid;
            int row = idx >> 3, seg = idx & 7;
            float4 v = *reinterpret_cast<const float4*>(
                &Bt[(size_t)(bn + row) * K + k0 + seg * 4]);
            uint32_t hx, lx, hy, ly, hz, lz, hw, lw;
            split2(v.x, hx, lx); split2(v.y, hy, ly);
            split2(v.z, hz, lz); split2(v.w, hw, lw);
            uint32_t byte = row * 128 + seg * 16;
            uint32_t sw = byte ^ ((byte >> 3) & 0x70);
            sts128(st + 2 * A_BYTES + sw, hx, hy, hz, hw);
            sts128(st + 2 * A_BYTES + B_BYTES + sw, lx, ly, lz, lw);
        }
        FENCE_ASYNC();
        __syncthreads();
        if (tid < 32) {
            if (elect1()) {
                uint64_t ah = mk_desc(st);
                uint64_t al = mk_desc(st + A_BYTES);
                uint64_t bh = mk_desc(st + 2 * A_BYTES);
                uint64_t bl = mk_desc(st + 2 * A_BYTES + B_BYTES);
                #pragma unroll
                for (int q = 0; q < 4; q++)
                    mma_tf32(tmem, ah + 2 * q, bh + 2 * q, idesc,
                             (c == 0 && q == 0) ? 0u : 1u);
                #pragma unroll
                for (int q = 0; q < 4; q++)
                    mma_tf32(tmem, ah + 2 * q, bl + 2 * q, idesc, 1u);
                #pragma unroll
                for (int q = 0; q < 4; q++)
                    mma_tf32(tmem, al + 2 * q, bh + 2 * q, idesc, 1u);
                T5_COMMIT(mb_empty + 8 * s);
            }
        }
    }
    if (tid < 32) {
        if (elect1()) T5_COMMIT(mb_done);
    }
    MBAR_WAIT(mb_done, 0);
    T5_FENCE_AFTER();

    // epilogue: warp w owns rows 32w..32w+31 (its TMEM subpartition)
    const int wid = tid >> 5, lid = tid & 31;
    const size_t rowoff = (size_t)(bm + wid * 32 + lid) * N + bn;
    #pragma unroll
    for (int b2 = 0; b2 < TN / 32; b2++) {
        uint32_t r[32];
        LDTM_X32(r, tmem + b2 * 32);
        T5_WAIT_LD();
        #pragma unroll
        for (int j = 0; j < 32; j += 4) {
            float4 o = make_float4(__uint_as_float(r[j]), __uint_as_float(r[j + 1]),
                                   __uint_as_float(r[j + 2]), __uint_as_float(r[j + 3]));
            *reinterpret_cast<float4*>(&C[rowoff + b2 * 32 + j]) = o;
        }
    }
    __syncthreads();
    if (tid < 32) T5_DEALLOC(tmem, 128);

#else  // ---------------- SIMT fallback (plain compute_103 pass) ----------
    extern __shared__ char smem[];
    float* As = reinterpret_cast<float*>(smem);            // [128][17]
    float* Bs = As + 128 * 17;                              // [TN][17]
    const int tid = threadIdx.x;
    const int bm = blockIdx.y * 128, bn = blockIdx.x * TN;
    const int tx = tid & 15, ty = tid >> 4;                 // 16 x 8
    constexpr int CPT = TN / 16;                            // cols per thread
    float acc[16][CPT];
    #pragma unroll
    for (int i = 0; i < 16; i++)
        #pragma unroll
        for (int j = 0; j < CPT; j++) acc[i][j] = 0.f;

    for (int k0 = 0; k0 < K; k0 += 16) {
        for (int idx = tid; idx < 128 * 16; idx += 128) {
            int r = idx >> 4, kk = idx & 15;
            As[r * 17 + kk] = A[(size_t)(bm + r) * K + k0 + kk];
        }
        for (int idx = tid; idx < TN * 16; idx += 128) {
            int r = idx >> 4, kk = idx & 15;
            Bs[r * 17 + kk] = Bt[(size_t)(bn + r) * K + k0 + kk];
        }
        __syncthreads();
        #pragma unroll
        for (int kk = 0; kk < 16; kk++) {
            float bv[CPT];
            #pragma unroll
            for (int j = 0; j < CPT; j++) bv[j] = Bs[(tx * CPT + j) * 17 + kk];
            #pragma unroll
            for (int i = 0; i < 16; i++) {
                float av = As[(ty * 16 + i) * 17 + kk];
                #pragma unroll
                for (int j = 0; j < CPT; j++)
                    acc[i][j] = fmaf(av, bv[j], acc[i][j]);
            }
        }
        __syncthreads();
    }
    #pragma unroll
    for (int i = 0; i < 16; i++)
        #pragma unroll
        for (int j = 0; j < CPT; j++)
            C[(size_t)(bm + ty * 16 + i) * N + bn + tx * CPT + j] = acc[i][j];
#endif
}

// ---------------- rope kernels ----------------
__global__ __launch_bounds__(256) void rope_q_kernel(
    float* __restrict__ Qr, const float* __restrict__ freqs)
{
    int idx = blockIdx.x * 256 + threadIdx.x;
    if (idx >= MROWS * Hh * (Rr / 2)) return;
    int m = idx >> 9;
    int rem = idx & 511;
    int h = rem >> 5;
    int i = rem & 31;
    int t = m & (Tt - 1);
    float f = freqs[t * (Rr / 2) + i];
    float s, c;
    sincosf(f, &s, &c);
    size_t base = (size_t)m * (Hh * Rr) + h * Rr + 2 * i;
    float x0 = Qr[base], x1 = Qr[base + 1];
    Qr[base]     = x0 * c - x1 * s;
    Qr[base + 1] = x0 * s + x1 * c;
}

__global__ __launch_bounds__(256) void rope_k_kernel(
    const float* __restrict__ KRin, const float* __restrict__ freqs,
    float* __restrict__ KRout)
{
    int idx = blockIdx.x * 256 + threadIdx.x;
    if (idx >= MROWS * (Rr / 2)) return;
    int m = idx >> 5;
    int i = idx & 31;
    int t = m & (Tt - 1);
    float f = freqs[t * (Rr / 2) + i];
    float s, c;
    sincosf(f, &s, &c);
    size_t base = (size_t)m * Rr + 2 * i;
    float x0 = KRin[base], x1 = KRin[base + 1];
    KRout[base]     = x0 * c - x1 * s;
    KRout[base + 1] = x0 * s + x1 * c;
}

// ---------------- flash attention (fp32, causal) ----------------
#define SQS 196
#define SKS 196
#define SVS 132
#define SPS 68
#define FLASH_SMEM ((64*(SQS+SKS+SVS+SPS))*4)

__global__ __launch_bounds__(256) void flash_kernel(
    const float* __restrict__ Qc, const float* __restrict__ Qr,
    const float* __restrict__ Kc, const float* __restrict__ Kr,
    const float* __restrict__ V,  float* __restrict__ O)
{
    extern __shared__ float sm[];
    float* sQ = sm;
    float* sK = sQ + 64 * SQS;
    float* sV = sK + 64 * SKS;
    float* sP = sV + 64 * SVS;

    const int qt = blockIdx.x, h = blockIdx.y, b = blockIdx.z;
    const int q0 = qt * 64;
    const int tid = threadIdx.x;
    const int tx = tid & 15, ty = tid >> 4;
    const float scale = 0.07216878364870323f;

    for (int idx = tid; idx < 64 * 48; idx += 256) {
        int r = idx / 48, c4 = (idx % 48) * 4;
        int m = b * Tt + q0 + r;
        float4 v;
        if (c4 < 128)
            v = *reinterpret_cast<const float4*>(&Qc[(size_t)m * (Hh*HD) + h * HD + c4]);
        else
            v = *reinterpret_cast<const float4*>(&Qr[(size_t)m * (Hh*Rr) + h * Rr + (c4 - 128)]);
        *reinterpret_cast<float4*>(&sQ[r * SQS + c4]) = v;
    }

    float o[2][4][4];
    #pragma unroll
    for (int hf = 0; hf < 2; hf++)
        #pragma unroll
        for (int ri = 0; ri < 4; ri++)
            #pragma unroll
            for (int j = 0; j < 4; j++) o[hf][ri][j] = 0.0f;
    float mrow[4] = {-INFINITY, -INFINITY, -INFINITY, -INFINITY};
    float lrow[4] = {0.f, 0.f, 0.f, 0.f};

    for (int kt = 0; kt <= qt; kt++) {
        const int k0 = kt * 64;
        __syncthreads();
        for (int idx = tid; idx < 64 * 48; idx += 256) {
            int r = idx / 48, c4 = (idx % 48) * 4;
            int mk = b * Tt + k0 + r;
            float4 v;
            if (c4 < 128)
                v = *reinterpret_cast<const float4*>(&Kc[(size_t)mk * (Hh*HD) + h * HD + c4]);
            else
                v = *reinterpret_cast<const float4*>(&Kr[(size_t)mk * Rr + (c4 - 128)]);
            *reinterpret_cast<float4*>(&sK[r * SKS + c4]) = v;
        }
        for (int idx = tid; idx < 64 * 32; idx += 256) {
            int r = idx / 32, c4 = (idx % 32) * 4;
            int mk = b * Tt + k0 + r;
            *reinterpret_cast<float4*>(&sV[r * SVS + c4]) =
                *reinterpret_cast<const float4*>(&V[(size_t)mk * (Hh*HD) + h * HD + c4]);
        }
        __syncthreads();

        float s[4][4];
        #pragma unroll
        for (int ri = 0; ri < 4; ri++)
            #pragma unroll
            for (int cj = 0; cj < 4; cj++) s[ri][cj] = 0.0f;

        #pragma unroll 4
        for (int k4 = 0; k4 < 192; k4 += 4) {
            float4 a[4], bb[4];
            #pragma unroll
            for (int ri = 0; ri < 4; ri++)
                a[ri] = *reinterpret_cast<const float4*>(&sQ[(ty * 4 + ri) * SQS + k4]);
            #pragma unroll
            for (int cj = 0; cj < 4; cj++)
                bb[cj] = *reinterpret_cast<const float4*>(&sK[(tx + cj * 16) * SKS + k4]);
            #pragma unroll
            for (int ri = 0; ri < 4; ri++)
                #pragma unroll
                for (int cj = 0; cj < 4; cj++) {
                    s[ri][cj] = fmaf(a[ri].x, bb[cj].x, s[ri][cj]);
                    s[ri][cj] = fmaf(a[ri].y, bb[cj].y, s[ri][cj]);
                    s[ri][cj] = fmaf(a[ri].z, bb[cj].z, s[ri][cj]);
                    s[ri][cj] = fmaf(a[ri].w, bb[cj].w, s[ri][cj]);
                }
        }

        const bool diag = (kt == qt);
        #pragma unroll
        for (int ri = 0; ri < 4; ri++) {
            int qg = q0 + ty * 4 + ri;
            #pragma unroll
            for (int cj = 0; cj < 4; cj++) {
                int kg = k0 + tx + cj * 16;
                s[ri][cj] *= scale;
                if (diag && kg > qg) s[ri][cj] = -INFINITY;
            }
        }

        #pragma unroll
        for (int ri = 0; ri < 4; ri++) {
            float mx = fmaxf(fmaxf(s[ri][0], s[ri][1]), fmaxf(s[ri][2], s[ri][3]));
            #pragma unroll
            for (int off = 8; off >= 1; off >>= 1)
                mx = fmaxf(mx, __shfl_xor_sync(0xffffffffu, mx, off));
            float mnew = fmaxf(mrow[ri], mx);
            float p0 = __expf(s[ri][0] - mnew);
            float p1 = __expf(s[ri][1] - mnew);
            float p2 = __expf(s[ri][2] - mnew);
            float p3 = __expf(s[ri][3] - mnew);
            float rs = p0 + p1 + p2 + p3;
            #pragma unroll
            for (int off = 8; off >= 1; off >>= 1)
                rs += __shfl_xor_sync(0xffffffffu, rs, off);
            float alpha = __expf(mrow[ri] - mnew);
            lrow[ri] = lrow[ri] * alpha + rs;
            mrow[ri] = mnew;
            #pragma unroll
            for (int hf = 0; hf < 2; hf++)
                #pragma unroll
                for (int j = 0; j < 4; j++) o[hf][ri][j] *= alpha;
            int prow = (ty * 4 + ri) * SPS + tx;
            sP[prow +  0] = p0;
            sP[prow + 16] = p1;
            sP[prow + 32] = p2;
            sP[prow + 48] = p3;
        }
        __syncthreads();

        #pragma unroll 2
        for (int j4 = 0; j4 < 64; j4 += 4) {
            float pvv[4][4];
            #pragma unroll
            for (int ri = 0; ri < 4; ri++) {
                float4 t4 = *reinterpret_cast<const float4*>(&sP[(ty * 4 + ri) * SPS + j4]);
                pvv[ri][0] = t4.x; pvv[ri][1] = t4.y; pvv[ri][2] = t4.z; pvv[ri][3] = t4.w;
            }
            #pragma unroll
            for (int jj = 0; jj < 4; jj++) {
                float4 v0 = *reinterpret_cast<const float4*>(&sV[(j4 + jj) * SVS + tx * 4]);
                float4 v1 = *reinterpret_cast<const float4*>(&sV[(j4 + jj) * SVS + 64 + tx * 4]);
                #pragma unroll
                for (int ri = 0; ri < 4; ri++) {
                    float p = pvv[ri][jj];
                    o[0][ri][0] = fmaf(p, v0.x, o[0][ri][0]);
                    o[0][ri][1] = fmaf(p, v0.y, o[0][ri][1]);
                    o[0][ri][2] = fmaf(p, v0.z, o[0][ri][2]);
                    o[0][ri][3] = fmaf(p, v0.w, o[0][ri][3]);
                    o[1][ri][0] = fmaf(p, v1.x, o[1][ri][0]);
                    o[1][ri][1] = fmaf(p, v1.y, o[1][ri][1]);
                    o[1][ri][2] = fmaf(p, v1.z, o[1][ri][2]);
                    o[1][ri][3] = fmaf(p, v1.w, o[1][ri][3]);
                }
            }
        }
    }

    #pragma unroll
    for (int ri = 0; ri < 4; ri++) {
        float inv = 1.0f / lrow[ri];
        int m = b * Tt + q0 + ty * 4 + ri;
        float4 r0 = make_float4(o[0][ri][0] * inv, o[0][ri][1] * inv,
                                o[0][ri][2] * inv, o[0][ri][3] * inv);
        float4 r1 = make_float4(o[1][ri][0] * inv, o[1][ri][1] * inv,
                                o[1][ri][2] * inv, o[1][ri][3] * inv);
        *reinterpret_cast<float4*>(&O[(size_t)m * (Hh*HD) + h * HD + tx * 4]) = r0;
        *reinterpret_cast<float4*>(&O[(size_t)m * (Hh*HD) + h * HD + 64 + tx * 4]) = r1;
    }
}

// ---------------- launch ----------------
#define TG_SMEM_T(TN) (2048 + 3 * (2 * 128 * 128 + 2 * (TN) * 128))
#define TG_SMEM_F(TN) ((128 * 17 + (TN) * 17) * 4)
#define TG_SMEM(TN) (TG_SMEM_T(TN) > TG_SMEM_F(TN) ? TG_SMEM_T(TN) : TG_SMEM_F(TN))

extern "C" void kernel_launch(void* const* d_in, const int* in_sizes, int n_in,
                              void* d_out, int out_size)
{
    const float* x     = (const float*)d_in[0];
    const float* freqs = (const float*)d_in[1];
    const float* W_DKV = (const float*)d_in[2];
    const float* W_UK  = (const float*)d_in[3];
    const float* W_UV  = (const float*)d_in[4];
    const float* W_KR  = (const float*)d_in[5];
    const float* W_DQ  = (const float*)d_in[6];
    const float* W_UQ  = (const float*)d_in[7];
    const float* W_QR  = (const float*)d_in[8];
    const float* W_O   = (const float*)d_in[9];

    float* y   = (float*)d_out;
    float* cKV = y   + (size_t)Bb * Tt * DM;
    float* KRo = cKV + (size_t)Bb * Tt * KVL;

    float *pKc, *pV, *pcQ, *pQc, *pQr, *pKR, *pAO, *pWt;
    cudaGetSymbolAddress((void**)&pKc, g_Kc);
    cudaGetSymbolAddress((void**)&pV,  g_V);
    cudaGetSymbolAddress((void**)&pcQ, g_cQ);
    cudaGetSymbolAddress((void**)&pQc, g_Qc);
    cudaGetSymbolAddress((void**)&pQr, g_Qr);
    cudaGetSymbolAddress((void**)&pKR, g_KR);
    cudaGetSymbolAddress((void**)&pAO, g_AO);
    cudaGetSymbolAddress((void**)&pWt, g_Wt);

    cudaFuncSetAttribute(flash_kernel,
                         cudaFuncAttributeMaxDynamicSharedMemorySize, FLASH_SMEM);
    cudaFuncSetAttribute(tgemm_kernel<128>,
                         cudaFuncAttributeMaxDynamicSharedMemorySize, TG_SMEM(128));
    cudaFuncSetAttribute(tgemm_kernel<64>,
                         cudaFuncAttributeMaxDynamicSharedMemorySize, TG_SMEM(64));

    dim3 tb(32, 8);
    transpose_kernel<<<dim3(KVL/32,  DM/32),  tb>>>(W_DKV, pWt + O_DKV, DM, KVL);
    transpose_kernel<<<dim3((Hh*HD)/32, KVL/32), tb>>>(W_UK, pWt + O_UK, KVL, Hh*HD);
    transpose_kernel<<<dim3((Hh*HD)/32, KVL/32), tb>>>(W_UV, pWt + O_UV, KVL, Hh*HD);
    transpose_kernel<<<dim3(Rr/32,   DM/32),  tb>>>(W_KR, pWt + O_KR, DM, Rr);
    transpose_kernel<<<dim3(QL/32,   DM/32),  tb>>>(W_DQ, pWt + O_DQ, DM, QL);
    transpose_kernel<<<dim3((Hh*HD)/32, QL/32), tb>>>(W_UQ, pWt + O_UQ, QL, Hh*HD);
    transpose_kernel<<<dim3((Hh*Rr)/32, QL/32), tb>>>(W_QR, pWt + O_QR, QL, Hh*Rr);
    transpose_kernel<<<dim3(DM/32,   (Hh*HD)/32), tb>>>(W_O, pWt + O_O, Hh*HD, DM);

    // GEMMs (tcgen05 tf32x3)
    tgemm_kernel<128><<<dim3(KVL/128, MROWS/128), 128, TG_SMEM(128)>>>(
        x, pWt + O_DKV, cKV, KVL, DM);
    tgemm_kernel<128><<<dim3((Hh*HD)/128, MROWS/128), 128, TG_SMEM(128)>>>(
        cKV, pWt + O_UK, pKc, Hh*HD, KVL);
    tgemm_kernel<128><<<dim3((Hh*HD)/128, MROWS/128), 128, TG_SMEM(128)>>>(
        cKV, pWt + O_UV, pV, Hh*HD, KVL);
    tgemm_kernel<64><<<dim3(1, MROWS/128), 128, TG_SMEM(64)>>>(
        x, pWt + O_KR, pKR, Rr, DM);
    {
        int n = MROWS * (Rr / 2);
        rope_k_kernel<<<(n + 255) / 256, 256>>>(pKR, freqs, KRo);
    }
    tgemm_kernel<128><<<dim3(QL/128, MROWS/128), 128, TG_SMEM(128)>>>(
        x, pWt + O_DQ, pcQ, QL, DM);
    tgemm_kernel<128><<<dim3((Hh*HD)/128, MROWS/128), 128, TG_SMEM(128)>>>(
        pcQ, pWt + O_UQ, pQc, Hh*HD, QL);
    tgemm_kernel<128><<<dim3((Hh*Rr)/128, MROWS/128), 128, TG_SMEM(128)>>>(
        pcQ, pWt + O_QR, pQr, Hh*Rr, QL);
    {
        int n = MROWS * Hh * (Rr / 2);
        rope_q_kernel<<<(n + 255) / 256, 256>>>(pQr, freqs);
    }
    {
        dim3 grid(Tt / 64, Hh, Bb);
        flash_kernel<<<grid, 256, FLASH_SMEM>>>(pQc, pQr, pKc, KRo, pV, pAO);
    }
    tgemm_kernel<128><<<dim3(DM/128, MROWS/128), 128, TG_SMEM(128)>>>(
        pAO, pWt + O_O, y, DM, Hh*HD);
}

// round 4
// speedup vs baseline: 1.2814x; 1.0809x over previous
#include <cuda_runtime.h>
#include <math.h>
#include <float.h>
#include <stdint.h>

// ---------------- problem constants ----------------
#define Bb 2
#define Tt 2048
#define DM 2048
#define Hh 16
#define HD 128
#define KVL 512
#define QL 1024
#define Rr 64
#define MROWS (Bb*Tt)        // 4096
#define BH (Bb*Hh)           // 32

#if defined(__CUDA_ARCH_FEAT_SM103_ALL) || defined(__CUDA_ARCH_FEAT_SM100_ALL)
#define HAS_TCGEN05 1
#else
#define HAS_TCGEN05 0
#endif

// ---------------- scratch (device globals) ----------
__device__ float g_Kc[MROWS * (Hh*HD)];
__device__ float g_V [MROWS * (Hh*HD)];
__device__ float g_Vt[BH * HD * Tt];      // per-head V^T: [bh][d][t]
__device__ float g_cQ[MROWS * QL];
__device__ float g_Qc[MROWS * (Hh*HD)];
__device__ float g_Qr[MROWS * (Hh*Rr)];
__device__ float g_KR[MROWS * Rr];
__device__ float g_AO[MROWS * (Hh*HD)];
__device__ float g_S [(size_t)BH * Tt * Tt];   // scores/probs, 536 MB
// transposed weights (concatenated)
#define O_DKV 0
#define O_UK  (O_DKV + 512*2048)
#define O_UV  (O_UK  + 2048*512)
#define O_KR  (O_UV  + 2048*512)
#define O_DQ  (O_KR  + 64*2048)
#define O_UQ  (O_DQ  + 1024*2048)
#define O_QR  (O_UQ  + 2048*1024)
#define O_O   (O_QR  + 2048*1024)
#define WT_TOTAL (O_O + 2048*2048)
__device__ float g_Wt[WT_TOTAL];

// ---------------- PTX helpers (tcgen05 gated) ----------------
__device__ __forceinline__ uint32_t smem_u32(const void* p) {
    uint32_t a;
    asm("{ .reg .u64 t; cvta.to.shared.u64 t, %1; cvt.u32.u64 %0, t; }"
        : "=r"(a) : "l"(p));
    return a;
}

#if HAS_TCGEN05
__device__ __forceinline__ bool elect1() {
    uint32_t r;
    asm volatile("{\n\t.reg .pred p;\n\telect.sync _|p, 0xFFFFFFFF;\n\t"
                 "selp.b32 %0,1,0,p;\n\t}" : "=r"(r));
    return r != 0;
}
#define MBAR_INIT(a, c) \
    asm volatile("mbarrier.init.shared.b64 [%0], %1;" :: "r"(a), "r"(c) : "memory")
#define MBAR_WAIT(a, ph) do { \
    uint32_t _m = (a), _p = (uint32_t)(ph), _d; \
    asm volatile("{\n\t.reg .pred p;\n\t" \
        "mbarrier.try_wait.parity.acquire.cta.shared::cta.b64 p, [%1], %2;\n\t" \
        "selp.b32 %0,1,0,p;\n\t}" : "=r"(_d) : "r"(_m), "r"(_p) : "memory"); \
    while (!_d) { \
        asm volatile("{\n\t.reg .pred p;\n\t" \
            "mbarrier.try_wait.parity.acquire.cta.shared::cta.b64 p, [%1], %2, 0x989680;\n\t" \
            "selp.b32 %0,1,0,p;\n\t}" : "=r"(_d) : "r"(_m), "r"(_p) : "memory"); \
    } } while (0)
#define T5_COMMIT(a) \
    asm volatile("tcgen05.commit.cta_group::1.mbarrier::arrive::one.shared::cluster.b64 [%0];" \
                 :: "r"(a) : "memory")
#define T5_ALLOC(a, n) \
    asm volatile("tcgen05.alloc.cta_group::1.sync.aligned.shared::cta.b32 [%0], %1;" \
                 :: "r"(a), "r"(n) : "memory")
#define T5_DEALLOC(t, n) \
    asm volatile("tcgen05.dealloc.cta_group::1.sync.aligned.b32 %0, %1;" :: "r"(t), "r"(n))
#define T5_RELINQ() \
    asm volatile("tcgen05.relinquish_alloc_permit.cta_group::1.sync.aligned;")
#define T5_WAIT_LD()   asm volatile("tcgen05.wait::ld.sync.aligned;" ::: "memory")
#define T5_FENCE_AFTER() asm volatile("tcgen05.fence::after_thread_sync;" ::: "memory")
#define FENCE_ASYNC()  asm volatile("fence.proxy.async.shared::cta;" ::: "memory")

#define LDTM_X32(r, addr) \
    asm volatile("tcgen05.ld.sync.aligned.32x32b.x32.b32 " \
        "{%0, %1, %2, %3, %4, %5, %6, %7, %8, %9, %10, %11, %12, %13, %14, %15, " \
        "%16, %17, %18, %19, %20, %21, %22, %23, %24, %25, %26, %27, %28, %29, %30, %31}, [%32];" \
        : "=r"((r)[0]),  "=r"((r)[1]),  "=r"((r)[2]),  "=r"((r)[3]), \
          "=r"((r)[4]),  "=r"((r)[5]),  "=r"((r)[6]),  "=r"((r)[7]), \
          "=r"((r)[8]),  "=r"((r)[9]),  "=r"((r)[10]), "=r"((r)[11]), \
          "=r"((r)[12]), "=r"((r)[13]), "=r"((r)[14]), "=r"((r)[15]), \
          "=r"((r)[16]), "=r"((r)[17]), "=r"((r)[18]), "=r"((r)[19]), \
          "=r"((r)[20]), "=r"((r)[21]), "=r"((r)[22]), "=r"((r)[23]), \
          "=r"((r)[24]), "=r"((r)[25]), "=r"((r)[26]), "=r"((r)[27]), \
          "=r"((r)[28]), "=r"((r)[29]), "=r"((r)[30]), "=r"((r)[31]) \
        : "r"(addr))

__device__ __forceinline__ void mma_tf32(uint32_t d, uint64_t ad, uint64_t bd,
                                         uint32_t idesc, uint32_t en) {
    asm volatile("{\n\t.reg .pred p;\n\tsetp.ne.u32 p, %4, 0;\n\t"
        "tcgen05.mma.cta_group::1.kind::tf32 [%0], %1, %2, %3, p;\n\t}"
        :: "r"(d), "l"(ad), "l"(bd), "r"(idesc), "r"(en) : "memory");
}
__device__ __forceinline__ uint64_t mk_desc(uint32_t addr) {
    // SW128 K-major: layout=2, version=1, SBO=64, LBO=1
    return ((uint64_t)2 << 61) | ((uint64_t)1 << 46) | ((uint64_t)64 << 32)
         | ((uint64_t)1 << 16) | ((addr >> 4) & 0x3FFF);
}
#endif  // HAS_TCGEN05

__device__ __forceinline__ void split2(float v, uint32_t& h, uint32_t& l) {
    uint32_t u = __float_as_uint(v);
    h = u & 0xFFFFE000u;                         // exact tf32 truncation
    l = __float_as_uint(v - __uint_as_float(h)); // exact residual
}
__device__ __forceinline__ void sts128(uint32_t addr, uint32_t a, uint32_t b,
                                       uint32_t c, uint32_t d) {
    asm volatile("st.shared.v4.b32 [%0], {%1,%2,%3,%4};"
                 :: "r"(addr), "r"(a), "r"(b), "r"(c), "r"(d) : "memory");
}

// split a float4 and store hi/lo tiles at swizzled offset
__device__ __forceinline__ void split_sts(uint32_t base_hi, uint32_t base_lo,
                                          int row, int seg, float4 v) {
    uint32_t hx, lx, hy, ly, hz, lz, hw, lw;
    split2(v.x, hx, lx); split2(v.y, hy, ly);
    split2(v.z, hz, lz); split2(v.w, hw, lw);
    uint32_t byte = row * 128 + seg * 16;
    uint32_t sw = byte ^ ((byte >> 3) & 0x70);
    sts128(base_hi + sw, hx, hy, hz, hw);
    sts128(base_lo + sw, lx, ly, lz, lw);
}

// ---------------- weight transpose: Wt[n][k] = W[k][n] ----------------
__global__ __launch_bounds__(256) void transpose_kernel(
    const float* __restrict__ W, float* __restrict__ Wt, int K, int N)
{
    __shared__ float t[32][33];
    int n0 = blockIdx.x * 32, k0 = blockIdx.y * 32;
    #pragma unroll
    for (int i = threadIdx.y; i < 32; i += 8)
        t[i][threadIdx.x] = W[(size_t)(k0 + i) * N + n0 + threadIdx.x];
    __syncthreads();
    #pragma unroll
    for (int i = threadIdx.y; i < 32; i += 8)
        Wt[(size_t)(n0 + i) * K + k0 + threadIdx.x] = t[threadIdx.x][i];
}

// per-head V transpose: Vt[bh][d][t] = V[(b t),(h d)]
__global__ __launch_bounds__(256) void transpose_v_kernel(
    const float* __restrict__ V, float* __restrict__ Vt)
{
    __shared__ float t[32][33];
    int bh = blockIdx.z;
    int b = bh >> 4, h = bh & 15;
    int t0 = blockIdx.x * 32, d0 = blockIdx.y * 32;
    #pragma unroll
    for (int i = threadIdx.y; i < 32; i += 8)
        t[i][threadIdx.x] = V[(size_t)(b * Tt + t0 + i) * (Hh*HD) + h * HD + d0 + threadIdx.x];
    __syncthreads();
    #pragma unroll
    for (int i = threadIdx.y; i < 32; i += 8)
        Vt[((size_t)bh * HD + d0 + i) * Tt + t0 + threadIdx.x] = t[threadIdx.x][i];
}

// ---------------- GEMM: C[M,N] = A[M,K] @ Bt[N,K]^T (tf32x3) ----------------
template<int TN>
__global__ __launch_bounds__(128) void tgemm_kernel(
    const float* __restrict__ A, const float* __restrict__ Bt,
    float* __restrict__ C, int N, int K)
{
#if HAS_TCGEN05
    constexpr int A_BYTES = 128 * 128;
    constexpr int B_BYTES = TN * 128;
    constexpr int STAGE = 2 * A_BYTES + 2 * B_BYTES;
    extern __shared__ char smem[];
    const uint32_t sbase = smem_u32(smem);
    const uint32_t mb_empty = sbase;
    const uint32_t mb_done  = sbase + 24;
    const uint32_t tmem_slot = sbase + 32;
    const uint32_t tiles = (sbase + 64 + 1023) & ~1023u;

    const int tid = threadIdx.x;
    const int bm = blockIdx.y * 128, bn = blockIdx.x * TN;

    if (tid == 0) {
        MBAR_INIT(mb_empty + 0, 1);
        MBAR_INIT(mb_empty + 8, 1);
        MBAR_INIT(mb_empty + 16, 1);
        MBAR_INIT(mb_done, 1);
    }
    if (tid < 32) { T5_ALLOC(tmem_slot, 128); T5_RELINQ(); }
    __syncthreads();
    uint32_t tmem;
    asm volatile("ld.shared.b32 %0, [%1];" : "=r"(tmem) : "r"(tmem_slot));

    const uint32_t idesc = (1u << 4) | (2u << 7) | (2u << 10)
                         | ((uint32_t)(TN / 8) << 17) | (8u << 24);
    const int nc = K >> 5;

    for (int c = 0; c < nc; c++) {
        const int s = c - (c / 3) * 3;
        const uint32_t st = tiles + s * STAGE;
        if (c >= 3) MBAR_WAIT(mb_empty + 8 * s, ((c / 3) - 1) & 1);
        const int k0 = c * 32;
        #pragma unroll
        for (int i = 0; i < 8; i++) {
            int idx = i * 128 + tid;
            int row = idx >> 3, seg = idx & 7;
            float4 v = *reinterpret_cast<const float4*>(
                &A[(size_t)(bm + row) * K + k0 + seg * 4]);
            split_sts(st, st + A_BYTES, row, seg, v);
        }
        #pragma unroll
        for (int i = 0; i < TN / 16; i++) {
            int idx = i * 128 + tid;
            int row = idx >> 3, seg = idx & 7;
            float4 v = *reinterpret_cast<const float4*>(
                &Bt[(size_t)(bn + row) * K + k0 + seg * 4]);
            split_sts(st + 2 * A_BYTES, st + 2 * A_BYTES + B_BYTES, row, seg, v);
        }
        FENCE_ASYNC();
        __syncthreads();
        if (tid < 32 && elect1()) {
            uint64_t ah = mk_desc(st);
            uint64_t al = mk_desc(st + A_BYTES);
            uint64_t bh = mk_desc(st + 2 * A_BYTES);
            uint64_t bl = mk_desc(st + 2 * A_BYTES + B_BYTES);
            #pragma unroll
            for (int q = 0; q < 4; q++)
                mma_tf32(tmem, ah + 2 * q, bh + 2 * q, idesc,
                         (c == 0 && q == 0) ? 0u : 1u);
            #pragma unroll
            for (int q = 0; q < 4; q++)
                mma_tf32(tmem, ah + 2 * q, bl + 2 * q, idesc, 1u);
            #pragma unroll
            for (int q = 0; q < 4; q++)
                mma_tf32(tmem, al + 2 * q, bh + 2 * q, idesc, 1u);
            T5_COMMIT(mb_empty + 8 * s);
        }
    }
    if (tid < 32 && elect1()) T5_COMMIT(mb_done);
    MBAR_WAIT(mb_done, 0);
    T5_FENCE_AFTER();

    const int wid = tid >> 5, lid = tid & 31;
    const size_t rowoff = (size_t)(bm + wid * 32 + lid) * N + bn;
    #pragma unroll
    for (int b2 = 0; b2 < TN / 32; b2++) {
        uint32_t r[32];
        LDTM_X32(r, tmem + b2 * 32);
        T5_WAIT_LD();
        #pragma unroll
        for (int j = 0; j < 32; j += 4) {
            float4 o = make_float4(__uint_as_float(r[j]), __uint_as_float(r[j + 1]),
                                   __uint_as_float(r[j + 2]), __uint_as_float(r[j + 3]));
            *reinterpret_cast<float4*>(&C[rowoff + b2 * 32 + j]) = o;
        }
    }
    __syncthreads();
    if (tid < 32) T5_DEALLOC(tmem, 128);
#else
    // naive fallback (compiles on plain targets; never runs on GB300)
    const int tid = threadIdx.x;
    const int bm = blockIdx.y * 128, bn = blockIdx.x * TN;
    for (int e = tid; e < 128 * TN; e += 128) {
        int r = e / TN, c = e % TN;
        float acc = 0.f;
        for (int k = 0; k < K; k++)
            acc += A[(size_t)(bm + r) * K + k] * Bt[(size_t)(bn + c) * K + k];
        C[(size_t)(bm + r) * N + bn + c] = acc;
    }
#endif
}

// ---------------- S = Q K^T over causal tiles (tf32x3) ----------------
// grid (kt=16, qt=16, bh=32), block 128. K = 192 (128 from Qc/Kc + 64 rope).
__global__ __launch_bounds__(128) void sqk_kernel(
    const float* __restrict__ Qc, const float* __restrict__ Qr,
    const float* __restrict__ Kc, const float* __restrict__ Kr,
    float* __restrict__ S)
{
    const int kt = blockIdx.x, qt = blockIdx.y, bh = blockIdx.z;
    if (kt > qt) return;
#if HAS_TCGEN05
    constexpr int A_BYTES = 128 * 128;
    constexpr int STAGE = 4 * A_BYTES;   // A hi/lo + B hi/lo
    extern __shared__ char smem[];
    const uint32_t sbase = smem_u32(smem);
    const uint32_t mb_empty = sbase;
    const uint32_t mb_done  = sbase + 24;
    const uint32_t tmem_slot = sbase + 32;
    const uint32_t tiles = (sbase + 64 + 1023) & ~1023u;

    const int tid = threadIdx.x;
    const int b = bh >> 4, h = bh & 15;

    if (tid == 0) {
        MBAR_INIT(mb_empty + 0, 1);
        MBAR_INIT(mb_empty + 8, 1);
        MBAR_INIT(mb_empty + 16, 1);
        MBAR_INIT(mb_done, 1);
    }
    if (tid < 32) { T5_ALLOC(tmem_slot, 128); T5_RELINQ(); }
    __syncthreads();
    uint32_t tmem;
    asm volatile("ld.shared.b32 %0, [%1];" : "=r"(tmem) : "r"(tmem_slot));

    const uint32_t idesc = (1u << 4) | (2u << 7) | (2u << 10)
                         | (16u << 17) | (8u << 24);   // N=128, M=128

    const size_t qrow0 = (size_t)(b * Tt + qt * 128);
    const size_t krow0 = (size_t)(b * Tt + kt * 128);

    for (int c = 0; c < 6; c++) {
        const int s = c - (c / 3) * 3;
        const uint32_t st = tiles + s * STAGE;
        if (c >= 3) MBAR_WAIT(mb_empty + 8 * s, ((c / 3) - 1) & 1);
        const int k0 = c * 32;
        const bool rope = (k0 >= 128);
        const float* Ab = rope ? Qr + qrow0 * (Hh*Rr) + h * Rr + (k0 - 128)
                               : Qc + qrow0 * (Hh*HD) + h * HD + k0;
        const float* Bb2 = rope ? Kr + krow0 * Rr + (k0 - 128)
                                : Kc + krow0 * (Hh*HD) + h * HD + k0;
        const int Astr = rope ? (Hh*Rr) : (Hh*HD);
        const int Bstr = rope ? Rr : (Hh*HD);
        #pragma unroll
        for (int i = 0; i < 8; i++) {
            int idx = i * 128 + tid;
            int row = idx >> 3, seg = idx & 7;
            float4 v = *reinterpret_cast<const float4*>(&Ab[(size_t)row * Astr + seg * 4]);
            split_sts(st, st + A_BYTES, row, seg, v);
        }
        #pragma unroll
        for (int i = 0; i < 8; i++) {
            int idx = i * 128 + tid;
            int row = idx >> 3, seg = idx & 7;
            float4 v = *reinterpret_cast<const float4*>(&Bb2[(size_t)row * Bstr + seg * 4]);
            split_sts(st + 2 * A_BYTES, st + 3 * A_BYTES, row, seg, v);
        }
        FENCE_ASYNC();
        __syncthreads();
        if (tid < 32 && elect1()) {
            uint64_t ah = mk_desc(st);
            uint64_t al = mk_desc(st + A_BYTES);
            uint64_t bhd = mk_desc(st + 2 * A_BYTES);
            uint64_t bld = mk_desc(st + 3 * A_BYTES);
            #pragma unroll
            for (int q = 0; q < 4; q++)
                mma_tf32(tmem, ah + 2 * q, bhd + 2 * q, idesc,
                         (c == 0 && q == 0) ? 0u : 1u);
            #pragma unroll
            for (int q = 0; q < 4; q++)
                mma_tf32(tmem, ah + 2 * q, bld + 2 * q, idesc, 1u);
            #pragma unroll
            for (int q = 0; q < 4; q++)
                mma_tf32(tmem, al + 2 * q, bhd + 2 * q, idesc, 1u);
            T5_COMMIT(mb_empty + 8 * s);
        }
    }
    if (tid < 32 && elect1()) T5_COMMIT(mb_done);
    MBAR_WAIT(mb_done, 0);
    T5_FENCE_AFTER();

    const int wid = tid >> 5, lid = tid & 31;
    const size_t rowoff = ((size_t)bh * Tt + qt * 128 + wid * 32 + lid) * Tt + kt * 128;
    #pragma unroll
    for (int b2 = 0; b2 < 4; b2++) {
        uint32_t r[32];
        LDTM_X32(r, tmem + b2 * 32);
        T5_WAIT_LD();
        #pragma unroll
        for (int j = 0; j < 32; j += 4) {
            float4 o = make_float4(__uint_as_float(r[j]), __uint_as_float(r[j + 1]),
                                   __uint_as_float(r[j + 2]), __uint_as_float(r[j + 3]));
            *reinterpret_cast<float4*>(&S[rowoff + b2 * 32 + j]) = o;
        }
    }
    __syncthreads();
    if (tid < 32) T5_DEALLOC(tmem, 128);
#else
    const int tid = threadIdx.x;
    const int b = bh >> 4, h = bh & 15;
    for (int e = tid; e < 128 * 128; e += 128) {
        int r = e >> 7, c = e & 127;
        int q = qt * 128 + r, k = kt * 128 + c;
        float acc = 0.f;
        for (int d = 0; d < 128; d++)
            acc += Qc[(size_t)(b*Tt+q)*(Hh*HD) + h*HD + d] * Kc[(size_t)(b*Tt+k)*(Hh*HD) + h*HD + d];
        for (int d = 0; d < 64; d++)
            acc += Qr[(size_t)(b*Tt+q)*(Hh*Rr) + h*Rr + d] * Kr[(size_t)(b*Tt+k)*Rr + d];
        S[((size_t)bh * Tt + q) * Tt + k] = acc;
    }
#endif
}

// ---------------- softmax over causal rows (normalizes P in place) --------
__global__ __launch_bounds__(256) void softmax_kernel(float* __restrict__ S)
{
    const float scale = 0.07216878364870323f;   // 1/sqrt(192)
    int gw = blockIdx.x * 8 + (threadIdx.x >> 5);
    int bh = gw >> 11, q = gw & 2047;
    int lane = threadIdx.x & 31;
    float* row = S + ((size_t)bh * Tt + q) * Tt;
    const int n = q + 1;
    const int ktE = ((q >> 7) + 1) * 128;   // end of diag tile

    // pass 1: online max+sum
    float m = -1e30f, l = 0.f;
    for (int i = lane * 4; i < ktE; i += 128) {
        float4 v = *reinterpret_cast<const float4*>(&row[i]);
        float vv[4] = {v.x, v.y, v.z, v.w};
        #pragma unroll
        for (int j = 0; j < 4; j++) {
            if (i + j < n) {
                float s = vv[j] * scale;
                if (s > m) { l = l * __expf(m - s) + 1.f; m = s; }
                else l += __expf(s - m);
            }
        }
    }
    #pragma unroll
    for (int off = 16; off >= 1; off >>= 1) {
        float mo = __shfl_xor_sync(0xffffffffu, m, off);
        float lo = __shfl_xor_sync(0xffffffffu, l, off);
        float M = fmaxf(m, mo);
        l = l * __expf(m - M) + lo * __expf(mo - M);
        m = M;
    }
    float invl = 1.0f / l;

    // pass 2: write normalized probs (zeros in diag-tile pad)
    for (int i = lane * 4; i < ktE; i += 128) {
        float4 v = *reinterpret_cast<const float4*>(&row[i]);
        float vv[4] = {v.x, v.y, v.z, v.w};
        float4 o;
        float* oo = &o.x;
        #pragma unroll
        for (int j = 0; j < 4; j++)
            oo[j] = (i + j < n) ? __expf(vv[j] * scale - m) * invl : 0.f;
        *reinterpret_cast<float4*>(&row[i]) = o;
    }
}

// ---------------- O = P @ V (tf32x3) ----------------
// grid (qt=16, bh=32), block 128. K = (qt+1)*128.
__global__ __launch_bounds__(128) void pv_kernel(
    const float* __restrict__ P, const float* __restrict__ Vt,
    float* __restrict__ O)
{
    const int qt = blockIdx.x, bh = blockIdx.y;
#if HAS_TCGEN05
    constexpr int A_BYTES = 128 * 128;
    constexpr int STAGE = 4 * A_BYTES;
    extern __shared__ char smem[];
    const uint32_t sbase = smem_u32(smem);
    const uint32_t mb_empty = sbase;
    const uint32_t mb_done  = sbase + 24;
    const uint32_t tmem_slot = sbase + 32;
    const uint32_t tiles = (sbase + 64 + 1023) & ~1023u;

    const int tid = threadIdx.x;
    const int b = bh >> 4, h = bh & 15;

    if (tid == 0) {
        MBAR_INIT(mb_empty + 0, 1);
        MBAR_INIT(mb_empty + 8, 1);
        MBAR_INIT(mb_empty + 16, 1);
        MBAR_INIT(mb_done, 1);
    }
    if (tid < 32) { T5_ALLOC(tmem_slot, 128); T5_RELINQ(); }
    __syncthreads();
    uint32_t tmem;
    asm volatile("ld.shared.b32 %0, [%1];" : "=r"(tmem) : "r"(tmem_slot));

    const uint32_t idesc = (1u << 4) | (2u << 7) | (2u << 10)
                         | (16u << 17) | (8u << 24);
    const int nc = (qt + 1) * 4;

    const float* Ab0 = P + ((size_t)bh * Tt + qt * 128) * Tt;
    const float* Bb0 = Vt + (size_t)bh * HD * Tt;

    for (int c = 0; c < nc; c++) {
        const int s = c - (c / 3) * 3;
        const uint32_t st = tiles + s * STAGE;
        if (c >= 3) MBAR_WAIT(mb_empty + 8 * s, ((c / 3) - 1) & 1);
        const int k0 = c * 32;
        #pragma unroll
        for (int i = 0; i < 8; i++) {
            int idx = i * 128 + tid;
            int row = idx >> 3, seg = idx & 7;
            float4 v = *reinterpret_cast<const float4*>(&Ab0[(size_t)row * Tt + k0 + seg * 4]);
            split_sts(st, st + A_BYTES, row, seg, v);
        }
        #pragma unroll
        for (int i = 0; i < 8; i++) {
            int idx = i * 128 + tid;
            int row = idx >> 3, seg = idx & 7;
            float4 v = *reinterpret_cast<const float4*>(&Bb0[(size_t)row * Tt + k0 + seg * 4]);
            split_sts(st + 2 * A_BYTES, st + 3 * A_BYTES, row, seg, v);
        }
        FENCE_ASYNC();
        __syncthreads();
        if (tid < 32 && elect1()) {
            uint64_t ah = mk_desc(st);
            uint64_t al = mk_desc(st + A_BYTES);
            uint64_t bhd = mk_desc(st + 2 * A_BYTES);
            uint64_t bld = mk_desc(st + 3 * A_BYTES);
            #pragma unroll
            for (int q = 0; q < 4; q++)
                mma_tf32(tmem, ah + 2 * q, bhd + 2 * q, idesc,
                         (c == 0 && q == 0) ? 0u : 1u);
            #pragma unroll
            for (int q = 0; q < 4; q++)
                mma_tf32(tmem, ah + 2 * q, bld + 2 * q, idesc, 1u);
            #pragma unroll
            for (int q = 0; q < 4; q++)
                mma_tf32(tmem, al + 2 * q, bhd + 2 * q, idesc, 1u);
            T5_COMMIT(mb_empty + 8 * s);
        }
    }
    if (tid < 32 && elect1()) T5_COMMIT(mb_done);
    MBAR_WAIT(mb_done, 0);
    T5_FENCE_AFTER();

    const int wid = tid >> 5, lid = tid & 31;
    const size_t rowoff = (size_t)(b * Tt + qt * 128 + wid * 32 + lid) * (Hh*HD) + h * HD;
    #pragma unroll
    for (int b2 = 0; b2 < 4; b2++) {
        uint32_t r[32];
        LDTM_X32(r, tmem + b2 * 32);
        T5_WAIT_LD();
        #pragma unroll
        for (int j = 0; j < 32; j += 4) {
            float4 o = make_float4(__uint_as_float(r[j]), __uint_as_float(r[j + 1]),
                                   __uint_as_float(r[j + 2]), __uint_as_float(r[j + 3]));
            *reinterpret_cast<float4*>(&O[rowoff + b2 * 32 + j]) = o;
        }
    }
    __syncthreads();
    if (tid < 32) T5_DEALLOC(tmem, 128);
#else
    const int tid = threadIdx.x;
    const int b = bh >> 4, h = bh & 15;
    const int K = (qt + 1) * 128;
    for (int e = tid; e < 128 * 128; e += 128) {
        int r = e >> 7, d = e & 127;
        float acc = 0.f;
        for (int k = 0; k < K; k++)
            acc += P[((size_t)bh * Tt + qt * 128 + r) * Tt + k]
                 * Vt[((size_t)bh * HD + d) * Tt + k];
        O[(size_t)(b * Tt + qt * 128 + r) * (Hh*HD) + h * HD + d] = acc;
    }
#endif
}

// ---------------- rope kernels ----------------
__global__ __launch_bounds__(256) void rope_q_kernel(
    float* __restrict__ Qr, const float* __restrict__ freqs)
{
    int idx = blockIdx.x * 256 + threadIdx.x;
    if (idx >= MROWS * Hh * (Rr / 2)) return;
    int m = idx >> 9;
    int rem = idx & 511;
    int h = rem >> 5;
    int i = rem & 31;
    int t = m & (Tt - 1);
    float f = freqs[t * (Rr / 2) + i];
    float s, c;
    sincosf(f, &s, &c);
    size_t base = (size_t)m * (Hh * Rr) + h * Rr + 2 * i;
    float x0 = Qr[base], x1 = Qr[base + 1];
    Qr[base]     = x0 * c - x1 * s;
    Qr[base + 1] = x0 * s + x1 * c;
}

__global__ __launch_bounds__(256) void rope_k_kernel(
    const float* __restrict__ KRin, const float* __restrict__ freqs,
    float* __restrict__ KRout)
{
    int idx = blockIdx.x * 256 + threadIdx.x;
    if (idx >= MROWS * (Rr / 2)) return;
    int m = idx >> 5;
    int i = idx & 31;
    int t = m & (Tt - 1);
    float f = freqs[t * (Rr / 2) + i];
    float s, c;
    sincosf(f, &s, &c);
    size_t base = (size_t)m * Rr + 2 * i;
    float x0 = KRin[base], x1 = KRin[base + 1];
    KRout[base]     = x0 * c - x1 * s;
    KRout[base + 1] = x0 * s + x1 * c;
}

// ---------------- launch ----------------
#define TG_SMEM(TN) (2048 + 3 * (2 * 128 * 128 + 2 * (TN) * 128))
#define ATT_SMEM    (2048 + 3 * 4 * 128 * 128)

extern "C" void kernel_launch(void* const* d_in, const int* in_sizes, int n_in,
                              void* d_out, int out_size)
{
    const float* x     = (const float*)d_in[0];
    const float* freqs = (const float*)d_in[1];
    const float* W_DKV = (const float*)d_in[2];
    const float* W_UK  = (const float*)d_in[3];
    const float* W_UV  = (const float*)d_in[4];
    const float* W_KR  = (const float*)d_in[5];
    const float* W_DQ  = (const float*)d_in[6];
    const float* W_UQ  = (const float*)d_in[7];
    const float* W_QR  = (const float*)d_in[8];
    const float* W_O   = (const float*)d_in[9];

    float* y   = (float*)d_out;
    float* cKV = y   + (size_t)Bb * Tt * DM;
    float* KRo = cKV + (size_t)Bb * Tt * KVL;

    float *pKc, *pV, *pVt, *pcQ, *pQc, *pQr, *pKR, *pAO, *pWt, *pS;
    cudaGetSymbolAddress((void**)&pKc, g_Kc);
    cudaGetSymbolAddress((void**)&pV,  g_V);
    cudaGetSymbolAddress((void**)&pVt, g_Vt);
    cudaGetSymbolAddress((void**)&pcQ, g_cQ);
    cudaGetSymbolAddress((void**)&pQc, g_Qc);
    cudaGetSymbolAddress((void**)&pQr, g_Qr);
    cudaGetSymbolAddress((void**)&pKR, g_KR);
    cudaGetSymbolAddress((void**)&pAO, g_AO);
    cudaGetSymbolAddress((void**)&pWt, g_Wt);
    cudaGetSymbolAddress((void**)&pS,  g_S);

    cudaFuncSetAttribute(tgemm_kernel<128>,
                         cudaFuncAttributeMaxDynamicSharedMemorySize, TG_SMEM(128));
    cudaFuncSetAttribute(tgemm_kernel<64>,
                         cudaFuncAttributeMaxDynamicSharedMemorySize, TG_SMEM(64));
    cudaFuncSetAttribute(sqk_kernel,
                         cudaFuncAttributeMaxDynamicSharedMemorySize, ATT_SMEM);
    cudaFuncSetAttribute(pv_kernel,
                         cudaFuncAttributeMaxDynamicSharedMemorySize, ATT_SMEM);

    dim3 tb(32, 8);
    transpose_kernel<<<dim3(KVL/32,  DM/32),  tb>>>(W_DKV, pWt + O_DKV, DM, KVL);
    transpose_kernel<<<dim3((Hh*HD)/32, KVL/32), tb>>>(W_UK, pWt + O_UK, KVL, Hh*HD);
    transpose_kernel<<<dim3((Hh*HD)/32, KVL/32), tb>>>(W_UV, pWt + O_UV, KVL, Hh*HD);
    transpose_kernel<<<dim3(Rr/32,   DM/32),  tb>>>(W_KR, pWt + O_KR, DM, Rr);
    transpose_kernel<<<dim3(QL/32,   DM/32),  tb>>>(W_DQ, pWt + O_DQ, DM, QL);
    transpose_kernel<<<dim3((Hh*HD)/32, QL/32), tb>>>(W_UQ, pWt + O_UQ, QL, Hh*HD);
    transpose_kernel<<<dim3((Hh*Rr)/32, QL/32), tb>>>(W_QR, pWt + O_QR, QL, Hh*Rr);
    transpose_kernel<<<dim3(DM/32,   (Hh*HD)/32), tb>>>(W_O, pWt + O_O, Hh*HD, DM);

    // projections
    tgemm_kernel<128><<<dim3(KVL/128, MROWS/128), 128, TG_SMEM(128)>>>(
        x, pWt + O_DKV, cKV, KVL, DM);
    tgemm_kernel<128><<<dim3((Hh*HD)/128, MROWS/128), 128, TG_SMEM(128)>>>(
        cKV, pWt + O_UK, pKc, Hh*HD, KVL);
    tgemm_kernel<128><<<dim3((Hh*HD)/128, MROWS/128), 128, TG_SMEM(128)>>>(
        cKV, pWt + O_UV, pV, Hh*HD, KVL);
    transpose_v_kernel<<<dim3(Tt/32, HD/32, BH), tb>>>(pV, pVt);
    tgemm_kernel<64><<<dim3(1, MROWS/128), 128, TG_SMEM(64)>>>(
        x, pWt + O_KR, pKR, Rr, DM);
    {
        int n = MROWS * (Rr / 2);
        rope_k_kernel<<<(n + 255) / 256, 256>>>(pKR, freqs, KRo);
    }
    tgemm_kernel<128><<<dim3(QL/128, MROWS/128), 128, TG_SMEM(128)>>>(
        x, pWt + O_DQ, pcQ, QL, DM);
    tgemm_kernel<128><<<dim3((Hh*HD)/128, MROWS/128), 128, TG_SMEM(128)>>>(
        pcQ, pWt + O_UQ, pQc, Hh*HD, QL);
    tgemm_kernel<128><<<dim3((Hh*Rr)/128, MROWS/128), 128, TG_SMEM(128)>>>(
        pcQ, pWt + O_QR, pQr, Hh*Rr, QL);
    {
        int n = MROWS * Hh * (Rr / 2);
        rope_q_kernel<<<(n + 255) / 256, 256>>>(pQr, freqs);
    }

    // attention: S = QK^T (causal tiles), softmax, O = P V
    sqk_kernel<<<dim3(16, 16, BH), 128, ATT_SMEM>>>(pQc, pQr, pKc, KRo, pS);
    softmax_kernel<<<(BH * Tt) / 8, 256>>>(pS);
    pv_kernel<<<dim3(16, BH), 128, ATT_SMEM>>>(pS, pVt, pAO);

    // output projection
    tgemm_kernel<128><<<dim3(DM/128, MROWS/128), 128, TG_SMEM(128)>>>(
        pAO, pWt + O_O, y, DM, Hh*HD);
}